// round 9
// baseline (speedup 1.0000x reference)
#include <cuda_runtime.h>

#define CC 64
#define BB 32
#define HH 80
#define WW 80
#define CELL (CC*BB)      // 2048 floats per cell tile
#define NCELLS (HH*WW)    // 6400 cells
#define GSU 66            // splatted-G smem row stride in ull (16B aligned)
#define HS3 12            // per-warp h buffer row stride in floats (48B, 16B-aligned)

// Static device scratch (allocation-free per harness rules)
__device__ float g_xT[NCELLS*CELL];          // x transposed to [i][j][c][b]
__device__ float g_hf[4][NCELLS*CELL];       // per-direction h fields, [i][j][c][b]
__device__ int   g_cnt[4][WW][4];            // per-(dir,col,b-group) rows-completed flags

typedef unsigned long long ull;

// ---------- packed-f32x2 helpers ----------
static __device__ __forceinline__ ull splat2(float x){
  unsigned int r = __float_as_uint(x);
  ull d; asm("mov.b64 %0, {%1,%2};" : "=l"(d) : "r"(r), "r"(r));
  return d;
}
static __device__ __forceinline__ void fma2(ull &d, ull a, ull b){
  asm("fma.rn.f32x2 %0, %1, %2, %0;" : "+l"(d) : "l"(a), "l"(b));
}
static __device__ __forceinline__ void unpack2(ull v, float &lo, float &hi){
  unsigned int a, b;
  asm("mov.b64 {%0,%1}, %2;" : "=r"(a), "=r"(b) : "l"(v));
  lo = __uint_as_float(a); hi = __uint_as_float(b);
}
static __device__ __forceinline__ int ld_acq(const int* p){
  int v; asm volatile("ld.global.acquire.gpu.b32 %0, [%1];" : "=r"(v) : "l"(p)); return v;
}
static __device__ __forceinline__ void st_rel(int* p, int v){
  asm volatile("st.global.release.gpu.b32 [%0], %1;" :: "l"(p), "r"(v));
}

// ---------- kernel 1: transpose x [B,C,H,W] -> g_xT [i][j][c][b]; zero flags ----------
__global__ void __launch_bounds__(256) k_transpose(const float* __restrict__ x){
  int bid = blockIdx.x;              // 800 blocks: (i, j-tile of 8)
  int i  = bid / 10;
  int j0 = (bid % 10) * 8;
  int t  = threadIdx.x;

  if (bid == 0){
    for (int z = t; z < 4*WW*4; z += 256) ((int*)g_cnt)[z] = 0;
  }

  int p0 = t * 8;                    // p = c*32 + b ; 8 consecutive p = fixed c, 8 b's
  int c  = p0 >> 5;
  int b0 = p0 & 31;

  float v[8][8];
  #pragma unroll
  for (int pi = 0; pi < 8; pi++){
    const float* src = x + (((b0+pi)*CC + c)*HH + i)*WW + j0;
    float4 q0 = *(const float4*)src;
    float4 q1 = *(const float4*)(src + 4);
    v[pi][0]=q0.x; v[pi][1]=q0.y; v[pi][2]=q0.z; v[pi][3]=q0.w;
    v[pi][4]=q1.x; v[pi][5]=q1.y; v[pi][6]=q1.z; v[pi][7]=q1.w;
  }
  #pragma unroll
  for (int jj = 0; jj < 8; jj++){
    float* dst = g_xT + (i*WW + j0 + jj)*CELL + p0;
    *(float4*)dst     = make_float4(v[0][jj], v[1][jj], v[2][jj], v[3][jj]);
    *(float4*)(dst+4) = make_float4(v[4][jj], v[5][jj], v[6][jj], v[7][jj]);
  }
}

// ---------- inner matmuls ----------
// Warp tile 64c x 8b; lane = (cg = lane>>1) x (bp = lane&1); thread tile 4c x 4b.
// Acc layout (proven): a[r][0] = row c0+r x (b0,b0+1) ; a[r][1] = row c0+r x (b0+2,b0+3).
// Vertical operand from warp-private smem h buffer (stride HS3).
static __device__ __forceinline__ void mm_acc_s(const ull* __restrict__ sG,
    const float* __restrict__ hb, int c0, int bloc, ull a[4][2]){
  #pragma unroll 8
  for (int k = 0; k < CC; k++){
    ulonglong2 g01 = *(const ulonglong2*)(sG + k*GSU + c0);
    ulonglong2 g23 = *(const ulonglong2*)(sG + k*GSU + c0 + 2);
    ulonglong2 hq  = *(const ulonglong2*)(hb + k*HS3 + bloc);
    fma2(a[0][0], g01.x, hq.x); fma2(a[0][1], g01.x, hq.y);
    fma2(a[1][0], g01.y, hq.x); fma2(a[1][1], g01.y, hq.y);
    fma2(a[2][0], g23.x, hq.x); fma2(a[2][1], g23.x, hq.y);
    fma2(a[3][0], g23.y, hq.x); fma2(a[3][1], g23.y, hq.y);
  }
}
// Horizontal operand read DIRECTLY from the left neighbor's published gmem cell
// (lc pre-offset to this warp's 8-b slice; stride BB floats per k).
static __device__ __forceinline__ void mm_acc_g(const ull* __restrict__ sG,
    const float* __restrict__ lc, int c0, int bloc, ull a[4][2]){
  #pragma unroll 8
  for (int k = 0; k < CC; k++){
    ulonglong2 g01 = *(const ulonglong2*)(sG + k*GSU + c0);
    ulonglong2 g23 = *(const ulonglong2*)(sG + k*GSU + c0 + 2);
    ulonglong2 hq  = *(const ulonglong2*)(lc + k*BB + bloc);
    fma2(a[0][0], g01.x, hq.x); fma2(a[0][1], g01.x, hq.y);
    fma2(a[1][0], g01.y, hq.x); fma2(a[1][1], g01.y, hq.y);
    fma2(a[2][0], g23.x, hq.x); fma2(a[2][1], g23.x, hq.y);
    fma2(a[3][0], g23.y, hq.x); fma2(a[3][1], g23.y, hq.y);
  }
}

// ---------- kernel 2: persistent DAG recurrence; warp = independent (dir,col,b-slice) engine ----------
extern __shared__ float smem_dyn[];

__global__ void __launch_bounds__(128, 2) k_dag(
    const float* __restrict__ w0v, const float* __restrict__ w0h,
    const float* __restrict__ w1v, const float* __restrict__ w1h,
    const float* __restrict__ w2v, const float* __restrict__ w2h,
    const float* __restrict__ w3v, const float* __restrict__ w3h)
{
  const int bid  = blockIdx.x;
  const int dir  = bid / WW;        // dependency points to lower bids only -> schedule-safe
  const int jcol = bid % WW;
  const int tid  = threadIdx.x;

  const float* gv; const float* gh;
  int fi, fj, doRelu;
  switch (dir){
    case 0:  gv=w0v; gh=w0h; fi=0; fj=0; doRelu=1; break;  // SE
    case 1:  gv=w1v; gh=w1h; fi=1; fj=0; doRelu=1; break;  // NE
    case 2:  gv=w2v; gh=w2h; fi=1; fj=1; doRelu=1; break;  // NW
    default: gv=w3v; gh=w3h; fi=0; fj=1; doRelu=0; break;  // SW (no ReLU in reference)
  }

  ull*   sGv   = (ull*)smem_dyn;            // [k][c] splatted, CC*GSU ull
  ull*   sGh   = sGv + CC*GSU;
  float* hbase = (float*)(sGh + CC*GSU);    // 4 warp-private h buffers of CC*HS3 floats

  for (int idx = tid; idx < 4096; idx += 128){
    int c = idx >> 6, k = idx & 63;         // idx = c*64 + k (row-major source)
    sGv[k*GSU + c] = splat2(gv[idx]);
    sGh[k*GSU + c] = splat2(gh[idx]);
  }
  for (int idx = tid; idx < 4*CC*HS3; idx += 128) hbase[idx] = 0.f;  // zero h buffers
  __syncthreads();                          // only CTA-wide bar (G + h init)

  const int lane = tid & 31, w = tid >> 5;  // w = b-group (8 b's)
  const int cg = lane >> 1, bp = lane & 1;
  const int c0   = cg * 4;                  // c base of thread tile (covers all 64 c per warp)
  const int bloc = bp * 4;                  // local b within the 8-wide slice
  const int bg   = w * 8;                   // warp's global b base

  float* hA = hbase + w*CC*HS3;             // warp-private vertical state [k][8b]

  float* out_dir = g_hf[dir];
  const int rj  = fj ? (WW-1-jcol) : jcol;
  const int rjL = fj ? (WW-jcol)   : (jcol-1);
  const int* pflag = &g_cnt[dir][(jcol > 0) ? (jcol-1) : 0][w];
  int* mflag = &g_cnt[dir][jcol][w];

  // ---- prefetch x for row 0 ----
  ulonglong2 xp[4];
  {
    const int ri0 = fi ? (HH-1) : 0;
    const float* xc = g_xT + (ri0*WW + rj)*CELL;
    #pragma unroll
    for (int r = 0; r < 4; r++)
      xp[r] = *(const ulonglong2*)(xc + (c0+r)*BB + bg + bloc);
  }

  for (int i = 0; i < HH; i++){
    const int ri = fi ? (HH-1-i) : i;

    // ---- acc init from prefetched x ----
    ull a[4][2];
    #pragma unroll
    for (int r = 0; r < 4; r++){ a[r][0] = xp[r].x; a[r][1] = xp[r].y; }

    // ---- vertical matmul (warp-private h_prev; no cross-warp dependency) ----
    mm_acc_s(sGv, hA, c0, bloc, a);

    // ---- prefetch x for next row (hidden under wait + mmGh) ----
    {
      const int in  = (i+1 < HH) ? (i+1) : i;
      const int rin = fi ? (HH-1-in) : in;
      const float* xc = g_xT + (rin*WW + rj)*CELL;
      #pragma unroll
      for (int r = 0; r < 4; r++)
        xp[r] = *(const ulonglong2*)(xc + (c0+r)*BB + bg + bloc);
    }

    // ---- wait own producer flag, then horizontal matmul straight from gmem ----
    if (jcol > 0){
      const int need = i + 1;
      while (ld_acq(pflag) < need) { }
      const float* lc = out_dir + (ri*WW + rjL)*CELL + bg;   // this warp's 8-b slice
      mm_acc_g(sGh, lc, c0, bloc, a);
    }

    // ---- epilogue: unpack, ReLU ----
    float o[4][4];                           // o[r][bb] = h[c0+r][bg+bloc+bb]
    #pragma unroll
    for (int r = 0; r < 4; r++){
      unpack2(a[r][0], o[r][0], o[r][1]);
      unpack2(a[r][1], o[r][2], o[r][3]);
    }
    if (doRelu){
      #pragma unroll
      for (int r = 0; r < 4; r++)
        #pragma unroll
        for (int bb = 0; bb < 4; bb++)
          o[r][bb] = fmaxf(o[r][bb], 0.f);
    }

    // ---- publish to gmem, per-warp release flag ----
    float* ocell = out_dir + (ri*WW + rj)*CELL;
    #pragma unroll
    for (int r = 0; r < 4; r++)
      *(float4*)(ocell + (c0+r)*BB + bg + bloc) = make_float4(o[r][0], o[r][1], o[r][2], o[r][3]);
    __syncwarp();                            // orders all lanes' STGs before lane0's release
    if (lane == 0) st_rel(mflag, i + 1);

    // ---- warp-private writeback: next row's h_prev ----
    #pragma unroll
    for (int r = 0; r < 4; r++)
      *(float4*)(hA + (c0+r)*HS3 + bloc) = make_float4(o[r][0], o[r][1], o[r][2], o[r][3]);
    __syncwarp();                            // cross-lane smem ordering within the warp
  }
}

// ---------- kernel 3: out[b][c][i][j] = sum over 4 dirs of g_hf[d][i][j][c][b] ----------
__global__ void __launch_bounds__(256) k_sum(float* __restrict__ out){
  int bid = blockIdx.x;              // 800 blocks: (i, j-tile of 8)
  int i  = bid / 10;
  int j0 = (bid % 10) * 8;
  int t  = threadIdx.x;
  int p0 = t * 8;                    // fixed c, 8 consecutive b
  int c  = p0 >> 5;
  int b0 = p0 & 31;

  float v[8][8];
  #pragma unroll
  for (int jj = 0; jj < 8; jj++){
    int cell = (i*WW + j0 + jj)*CELL;
    float4 s0 = make_float4(0.f,0.f,0.f,0.f);
    float4 s1 = make_float4(0.f,0.f,0.f,0.f);
    #pragma unroll
    for (int d = 0; d < 4; d++){
      const float* src = g_hf[d] + cell + p0;
      float4 q0 = *(const float4*)src;
      float4 q1 = *(const float4*)(src + 4);
      s0.x += q0.x; s0.y += q0.y; s0.z += q0.z; s0.w += q0.w;
      s1.x += q1.x; s1.y += q1.y; s1.z += q1.z; s1.w += q1.w;
    }
    v[0][jj]=s0.x; v[1][jj]=s0.y; v[2][jj]=s0.z; v[3][jj]=s0.w;
    v[4][jj]=s1.x; v[5][jj]=s1.y; v[6][jj]=s1.z; v[7][jj]=s1.w;
  }
  #pragma unroll
  for (int pi = 0; pi < 8; pi++){
    float* dst = out + ((b0+pi)*CC + c)*NCELLS + i*WW + j0;
    *(float4*)dst     = make_float4(v[pi][0], v[pi][1], v[pi][2], v[pi][3]);
    *(float4*)(dst+4) = make_float4(v[pi][4], v[pi][5], v[pi][6], v[pi][7]);
  }
}

extern "C" void kernel_launch(void* const* d_in, const int* in_sizes, int n_in,
                              void* d_out, int out_size){
  const float* x   = (const float*)d_in[0];
  const float* g1  = (const float*)d_in[1];
  const float* g2  = (const float*)d_in[2];
  const float* g4  = (const float*)d_in[3];
  const float* g5  = (const float*)d_in[4];
  const float* g7  = (const float*)d_in[5];
  const float* g8  = (const float*)d_in[6];
  const float* g10 = (const float*)d_in[7];
  const float* g11 = (const float*)d_in[8];

  const int smem_bytes = 2*CC*GSU*8 + 4*CC*HS3*4;  // 67,584 + 12,288 = 79,872 B
  (void)cudaFuncSetAttribute(k_dag, cudaFuncAttributeMaxDynamicSharedMemorySize, smem_bytes);

  k_transpose<<<800, 256>>>(x);
  k_dag<<<320, 128, smem_bytes>>>(g1, g2, g4, g5, g7, g8, g10, g11);
  k_sum<<<800, 256>>>((float*)d_out);
}

// round 10
// speedup vs baseline: 1.0586x; 1.0586x over previous
#include <cuda_runtime.h>

#define CC 64
#define BB 32
#define HH 80
#define WW 80
#define NP 40             // column pairs per direction
#define CELL (CC*BB)      // 2048 floats per cell tile
#define NCELLS (HH*WW)    // 6400 cells
#define GSU 64            // splatted-G smem row stride in ull
#define HS 20             // hA/hB row stride (floats)
#define HOS 16            // hOut row stride (floats)

// Static device scratch (allocation-free per harness rules)
__device__ float g_xT[NCELLS*CELL];          // x transposed to [i][j][c][b]
__device__ float g_hf[4][NCELLS*CELL];       // per-direction h fields, [i][j][c][b]
__device__ int   g_cnt[4][NP][4];            // per-(dir,pair) flags from the pair's j1, per (half,cpart)

typedef unsigned long long ull;

// ---------- packed-f32x2 helpers ----------
static __device__ __forceinline__ ull splat2(float x){
  unsigned int r = __float_as_uint(x);
  ull d; asm("mov.b64 %0, {%1,%2};" : "=l"(d) : "r"(r), "r"(r));
  return d;
}
static __device__ __forceinline__ void fma2(ull &d, ull a, ull b){
  asm("fma.rn.f32x2 %0, %1, %2, %0;" : "+l"(d) : "l"(a), "l"(b));
}
static __device__ __forceinline__ void unpack2(ull v, float &lo, float &hi){
  unsigned int a, b;
  asm("mov.b64 {%0,%1}, %2;" : "=r"(a), "=r"(b) : "l"(v));
  lo = __uint_as_float(a); hi = __uint_as_float(b);
}
static __device__ __forceinline__ int ld_acq(const int* p){
  int v; asm volatile("ld.global.acquire.gpu.b32 %0, [%1];" : "=r"(v) : "l"(p)); return v;
}
static __device__ __forceinline__ void st_rel(int* p, int v){
  asm volatile("st.global.release.gpu.b32 [%0], %1;" :: "l"(p), "r"(v));
}
static __device__ __forceinline__ void bar_sync(int id, int cnt){
  asm volatile("bar.sync %0, %1;" :: "r"(id), "r"(cnt) : "memory");
}

// ---------- kernel 1: transpose x [B,C,H,W] -> g_xT [i][j][c][b]; zero flags ----------
__global__ void __launch_bounds__(256) k_transpose(const float* __restrict__ x){
  int bid = blockIdx.x;              // 800 blocks: (i, j-tile of 8)
  int i  = bid / 10;
  int j0 = (bid % 10) * 8;
  int t  = threadIdx.x;

  if (bid == 0){
    for (int z = t; z < 4*NP*4; z += 256) ((int*)g_cnt)[z] = 0;
  }

  int p0 = t * 8;                    // p = c*32 + b ; 8 consecutive p = fixed c, 8 b's
  int c  = p0 >> 5;
  int b0 = p0 & 31;

  float v[8][8];
  #pragma unroll
  for (int pi = 0; pi < 8; pi++){
    const float* src = x + (((b0+pi)*CC + c)*HH + i)*WW + j0;
    float4 q0 = *(const float4*)src;
    float4 q1 = *(const float4*)(src + 4);
    v[pi][0]=q0.x; v[pi][1]=q0.y; v[pi][2]=q0.z; v[pi][3]=q0.w;
    v[pi][4]=q1.x; v[pi][5]=q1.y; v[pi][6]=q1.z; v[pi][7]=q1.w;
  }
  #pragma unroll
  for (int jj = 0; jj < 8; jj++){
    float* dst = g_xT + (i*WW + j0 + jj)*CELL + p0;
    *(float4*)dst     = make_float4(v[0][jj], v[1][jj], v[2][jj], v[3][jj]);
    *(float4*)(dst+4) = make_float4(v[4][jj], v[5][jj], v[6][jj], v[7][jj]);
  }
}

// ---------- inner matmul (R7-proven form; operand stride templated) ----------
// Warp tile 32c x 16b; lane = (cg=lane>>2) x (bp=lane&3); thread tile 4c x 4b.
// Acc layout: a[r][0] = row c0+r x (b0,b0+1) ; a[r][1] = row c0+r x (b0+2,b0+3).
template<int HSTR>
static __device__ __forceinline__ void mm_acc(const ull* __restrict__ sG,
    const float* __restrict__ hb, int c0, int bloc, ull a[4][2]){
  #pragma unroll 8
  for (int k = 0; k < CC; k++){
    ulonglong2 g01 = *(const ulonglong2*)(sG + k*GSU + c0);
    ulonglong2 g23 = *(const ulonglong2*)(sG + k*GSU + c0 + 2);
    ulonglong2 hq  = *(const ulonglong2*)(hb + k*HSTR + bloc);
    fma2(a[0][0], g01.x, hq.x); fma2(a[0][1], g01.x, hq.y);
    fma2(a[1][0], g01.y, hq.x); fma2(a[1][1], g01.y, hq.y);
    fma2(a[2][0], g23.x, hq.x); fma2(a[2][1], g23.x, hq.y);
    fma2(a[3][0], g23.y, hq.x); fma2(a[3][1], g23.y, hq.y);
  }
}

// ---------- kernel 2: persistent DAG recurrence; CTA = (dir, column-pair) ----------
// 8 warps: warp w -> cj = w>>2 (column in pair), h = (w>>1)&1 (b-half), cpart = w&1 (c-half).
// j1 runs one row behind j0; j1's horizontal operand comes from SMEM hOut (parity-buffered).
// Only j1 crosses CTAs (gmem flag + staged copy on the consumer side).
extern __shared__ float smem_dyn[];

__global__ void __launch_bounds__(256, 2) k_dag(
    const float* __restrict__ w0v, const float* __restrict__ w0h,
    const float* __restrict__ w1v, const float* __restrict__ w1h,
    const float* __restrict__ w2v, const float* __restrict__ w2h,
    const float* __restrict__ w3v, const float* __restrict__ w3h)
{
  const int bid  = blockIdx.x;
  const int dir  = bid / NP;        // dependency points to lower bids only -> schedule-safe
  const int jp   = bid % NP;
  const int tid  = threadIdx.x;

  const float* gvp; const float* ghp;
  int fi, fj, doRelu;
  switch (dir){
    case 0:  gvp=w0v; ghp=w0h; fi=0; fj=0; doRelu=1; break;  // SE
    case 1:  gvp=w1v; ghp=w1h; fi=1; fj=0; doRelu=1; break;  // NE
    case 2:  gvp=w2v; ghp=w2h; fi=1; fj=1; doRelu=1; break;  // NW
    default: gvp=w3v; ghp=w3h; fi=0; fj=1; doRelu=0; break;  // SW (no ReLU in reference)
  }

  ull*   sGv   = (ull*)smem_dyn;                // [k][c] splatted, CC*GSU ull = 32KB
  ull*   sGh   = sGv + CC*GSU;                  // 32KB
  float* hAb   = (float*)(sGh + CC*GSU);        // 4 engine hA buffers [CC][HS]
  float* hBb   = hAb + 4*CC*HS;                 // 2 half hB buffers [CC][HS] (j0 staging)
  float* hOutb = hBb + 2*CC*HS;                 // [half][parity][CC][HOS] (j0 -> j1)

  for (int idx = tid; idx < 4096; idx += 256){
    int c = idx >> 6, k = idx & 63;             // idx = c*64 + k (row-major source)
    sGv[k*GSU + c] = splat2(gvp[idx]);
    sGh[k*GSU + c] = splat2(ghp[idx]);
  }
  for (int idx = tid; idx < 4*CC*HS; idx += 256) hAb[idx] = 0.f;  // zero vertical state
  __syncthreads();

  const int lane = tid & 31, w = tid >> 5;
  const int cj = w >> 2, h = (w >> 1) & 1, cpart = w & 1;
  const int cg = lane >> 2, bp = lane & 3;
  const int c0   = cpart*32 + cg*4;
  const int bloc = bp*4;                        // local b within 16-wide half
  const int b0g  = h*16 + bloc;                 // global b
  const int tRow = cpart*32 + lane;             // staging k-row for this warp

  float* hA   = hAb + (cj*2 + h)*CC*HS;         // engine-private vertical state
  float* hB   = hBb + h*CC*HS;                  // j0-only cross-CTA staging
  float* hOut = hOutb + h*2*CC*HOS;             // + (parity)*CC*HOS

  float* out_dir = g_hf[dir];
  const int jint = 2*jp + cj;                   // internal column
  const int rj   = fj ? (WW-1-jint) : jint;     // actual column
  const int jL   = 2*jp - 1;                    // j0's left internal column (prev CTA's j1)
  const int rjL  = fj ? (WW-1-jL) : jL;
  const int* pflag = &g_cnt[dir][(jp > 0) ? (jp-1) : 0][h*2 + cpart];
  int* mflag = &g_cnt[dir][jp][h*2 + cpart];    // set by j1 warps only
  const int barA = 1 + h;                       // 128-thr: both columns, same half
  const int barB = 3 + cj*2 + h;                // 64-thr: engine-private

  // ---- prefetch x for this engine's row 0 ----
  ulonglong2 xp[4];
  {
    const int ri0 = fi ? (HH-1) : 0;
    const float* xc = g_xT + (ri0*WW + rj)*CELL;
    #pragma unroll
    for (int r = 0; r < 4; r++)
      xp[r] = *(const ulonglong2*)(xc + (c0+r)*BB + b0g);
  }

  for (int s = 0; s <= HH; s++){
    const int i = s - cj;                       // engine row this step
    const bool active = (i >= 0) && (i < HH);
    const int ri = fi ? (HH-1-i) : i;

    ull a[4][2];
    if (active){
      // acc init = prefetched x
      #pragma unroll
      for (int r = 0; r < 4; r++){ a[r][0] = xp[r].x; a[r][1] = xp[r].y; }

      // vertical matmul (engine-private hA; ordered by barB of previous step)
      mm_acc<HS>(sGv, hA, c0, bloc, a);

      // prefetch x for next row
      if (i + 1 < HH){
        const int rin = fi ? (HH-2-i) : (i+1);
        const float* xc = g_xT + (rin*WW + rj)*CELL;
        #pragma unroll
        for (int r = 0; r < 4; r++)
          xp[r] = *(const ulonglong2*)(xc + (c0+r)*BB + b0g);
      }

      // j0: wait cross-CTA producer, stage its half-slice into hB
      if (cj == 0 && jp > 0){
        const int need = i + 1;
        while (ld_acq(pflag) < need) { }
        const float* src = out_dir + (ri*WW + rjL)*CELL + tRow*BB + h*16;
        float4 l0 = *(const float4*)(src);
        float4 l1 = *(const float4*)(src + 4);
        float4 l2 = *(const float4*)(src + 8);
        float4 l3 = *(const float4*)(src + 12);
        float* dst = hB + tRow*HS;
        *(float4*)(dst + 0)  = l0;
        *(float4*)(dst + 4)  = l1;
        *(float4*)(dst + 8)  = l2;
        *(float4*)(dst + 12) = l3;
      }
    }
    bar_sync(barA, 128);                        // hB staged (j0) / hOut(i&1) from j0 visible (j1)

    if (active){
      // horizontal matmul
      if (cj == 0){
        if (jp > 0) mm_acc<HS>(sGh, hB, c0, bloc, a);
      } else {
        mm_acc<HOS>(sGh, hOut + (i&1)*CC*HOS, c0, bloc, a);
      }

      // epilogue: unpack, ReLU
      float o[4][4];                            // o[r][bb] = h[c0+r][b0g+bb]
      #pragma unroll
      for (int r = 0; r < 4; r++){
        unpack2(a[r][0], o[r][0], o[r][1]);
        unpack2(a[r][1], o[r][2], o[r][3]);
      }
      if (doRelu){
        #pragma unroll
        for (int r = 0; r < 4; r++)
          #pragma unroll
          for (int bb = 0; bb < 4; bb++)
            o[r][bb] = fmaxf(o[r][bb], 0.f);
      }

      // publish to gmem (needed by k_sum; j1's also feeds next CTA)
      float* ocell = out_dir + (ri*WW + rj)*CELL;
      #pragma unroll
      for (int r = 0; r < 4; r++)
        *(float4*)(ocell + (c0+r)*BB + b0g) = make_float4(o[r][0], o[r][1], o[r][2], o[r][3]);

      if (cj == 1){
        __syncwarp();                           // order warp's STGs before lane0's release
        if (lane == 0) st_rel(mflag, i + 1);
      } else {
        // j0: hand row to j1 via smem (parity buffer)
        float* od = hOut + (i&1)*CC*HOS;
        #pragma unroll
        for (int r = 0; r < 4; r++)
          *(float4*)(od + (c0+r)*HOS + bloc) = make_float4(o[r][0], o[r][1], o[r][2], o[r][3]);
      }

      // vertical state writeback
      #pragma unroll
      for (int r = 0; r < 4; r++)
        *(float4*)(hA + (c0+r)*HS + bloc) = make_float4(o[r][0], o[r][1], o[r][2], o[r][3]);
    }
    bar_sync(barB, 64);                         // hA(new) visible to engine partner
  }
}

// ---------- kernel 3: out[b][c][i][j] = sum over 4 dirs of g_hf[d][i][j][c][b] ----------
__global__ void __launch_bounds__(256) k_sum(float* __restrict__ out){
  int bid = blockIdx.x;              // 800 blocks: (i, j-tile of 8)
  int i  = bid / 10;
  int j0 = (bid % 10) * 8;
  int t  = threadIdx.x;
  int p0 = t * 8;                    // fixed c, 8 consecutive b
  int c  = p0 >> 5;
  int b0 = p0 & 31;

  float v[8][8];
  #pragma unroll
  for (int jj = 0; jj < 8; jj++){
    int cell = (i*WW + j0 + jj)*CELL;
    float4 s0 = make_float4(0.f,0.f,0.f,0.f);
    float4 s1 = make_float4(0.f,0.f,0.f,0.f);
    #pragma unroll
    for (int d = 0; d < 4; d++){
      const float* src = g_hf[d] + cell + p0;
      float4 q0 = *(const float4*)src;
      float4 q1 = *(const float4*)(src + 4);
      s0.x += q0.x; s0.y += q0.y; s0.z += q0.z; s0.w += q0.w;
      s1.x += q1.x; s1.y += q1.y; s1.z += q1.z; s1.w += q1.w;
    }
    v[0][jj]=s0.x; v[1][jj]=s0.y; v[2][jj]=s0.z; v[3][jj]=s0.w;
    v[4][jj]=s1.x; v[5][jj]=s1.y; v[6][jj]=s1.z; v[7][jj]=s1.w;
  }
  #pragma unroll
  for (int pi = 0; pi < 8; pi++){
    float* dst = out + ((b0+pi)*CC + c)*NCELLS + i*WW + j0;
    *(float4*)dst     = make_float4(v[pi][0], v[pi][1], v[pi][2], v[pi][3]);
    *(float4*)(dst+4) = make_float4(v[pi][4], v[pi][5], v[pi][6], v[pi][7]);
  }
}

extern "C" void kernel_launch(void* const* d_in, const int* in_sizes, int n_in,
                              void* d_out, int out_size){
  const float* x   = (const float*)d_in[0];
  const float* g1  = (const float*)d_in[1];
  const float* g2  = (const float*)d_in[2];
  const float* g4  = (const float*)d_in[3];
  const float* g5  = (const float*)d_in[4];
  const float* g7  = (const float*)d_in[5];
  const float* g8  = (const float*)d_in[6];
  const float* g10 = (const float*)d_in[7];
  const float* g11 = (const float*)d_in[8];

  // G 65,536 + hA 20,480 + hB 10,240 + hOut 16,384 = 112,640 B  (2 CTAs/SM)
  const int smem_bytes = 2*CC*GSU*8 + 4*CC*HS*4 + 2*CC*HS*4 + 2*2*CC*HOS*4;
  (void)cudaFuncSetAttribute(k_dag, cudaFuncAttributeMaxDynamicSharedMemorySize, smem_bytes);

  k_transpose<<<800, 256>>>(x);
  k_dag<<<4*NP, 256, smem_bytes>>>(g1, g2, g4, g5, g7, g8, g10, g11);
  k_sum<<<800, 256>>>((float*)d_out);
}

// round 11
// speedup vs baseline: 1.3865x; 1.3097x over previous
#include <cuda_runtime.h>

#define CC 64
#define BB 32
#define HH 80
#define WW 80
#define CELL (CC*BB)      // 2048 floats per cell tile
#define NCELLS (HH*WW)    // 6400 cells
#define GSU 66            // splatted-G smem row stride in ull (16B aligned)
#define HS 20             // h buffer row stride in floats (R7-proven: 4-way STS conflicts only)

// Static device scratch (allocation-free per harness rules)
__device__ float g_xT[NCELLS*CELL];          // x transposed to [i][j][c][b]
__device__ float g_hf[4][NCELLS*CELL];       // per-direction h fields, [i][j][c][b]
__device__ int   g_cnt[4][WW][4];            // per-(dir,col,(cpart,half)) rows-completed flags

typedef unsigned long long ull;

// ---------- packed-f32x2 helpers ----------
static __device__ __forceinline__ ull splat2(float x){
  unsigned int r = __float_as_uint(x);
  ull d; asm("mov.b64 %0, {%1,%2};" : "=l"(d) : "r"(r), "r"(r));
  return d;
}
static __device__ __forceinline__ void fma2(ull &d, ull a, ull b){
  asm("fma.rn.f32x2 %0, %1, %2, %0;" : "+l"(d) : "l"(a), "l"(b));
}
static __device__ __forceinline__ void add2(ull &d, ull a){
  asm("add.rn.f32x2 %0, %0, %1;" : "+l"(d) : "l"(a));
}
static __device__ __forceinline__ void unpack2(ull v, float &lo, float &hi){
  unsigned int a, b;
  asm("mov.b64 {%0,%1}, %2;" : "=r"(a), "=r"(b) : "l"(v));
  lo = __uint_as_float(a); hi = __uint_as_float(b);
}
static __device__ __forceinline__ int ld_acq(const int* p){
  int v; asm volatile("ld.global.acquire.gpu.b32 %0, [%1];" : "=r"(v) : "l"(p)); return v;
}
static __device__ __forceinline__ void st_rel(int* p, int v){
  asm volatile("st.global.release.gpu.b32 [%0], %1;" :: "l"(p), "r"(v));
}
static __device__ __forceinline__ void bar64(int id){
  asm volatile("bar.sync %0, 64;" :: "r"(id) : "memory");
}

// ---------- kernel 1: transpose x [B,C,H,W] -> g_xT [i][j][c][b]; zero flags ----------
__global__ void __launch_bounds__(256) k_transpose(const float* __restrict__ x){
  int bid = blockIdx.x;              // 800 blocks: (i, j-tile of 8)
  int i  = bid / 10;
  int j0 = (bid % 10) * 8;
  int t  = threadIdx.x;

  if (bid == 0){
    for (int z = t; z < 4*WW*4; z += 256) ((int*)g_cnt)[z] = 0;
  }

  int p0 = t * 8;                    // p = c*32 + b ; 8 consecutive p = fixed c, 8 b's
  int c  = p0 >> 5;
  int b0 = p0 & 31;

  float v[8][8];
  #pragma unroll
  for (int pi = 0; pi < 8; pi++){
    const float* src = x + (((b0+pi)*CC + c)*HH + i)*WW + j0;
    float4 q0 = *(const float4*)src;
    float4 q1 = *(const float4*)(src + 4);
    v[pi][0]=q0.x; v[pi][1]=q0.y; v[pi][2]=q0.z; v[pi][3]=q0.w;
    v[pi][4]=q1.x; v[pi][5]=q1.y; v[pi][6]=q1.z; v[pi][7]=q1.w;
  }
  #pragma unroll
  for (int jj = 0; jj < 8; jj++){
    float* dst = g_xT + (i*WW + j0 + jj)*CELL + p0;
    *(float4*)dst     = make_float4(v[0][jj], v[1][jj], v[2][jj], v[3][jj]);
    *(float4*)(dst+4) = make_float4(v[4][jj], v[5][jj], v[6][jj], v[7][jj]);
  }
}

// ---------- inner matmul (R7-proven) ----------
// Warp tile 32c x 16b; lane = (cg=lane>>2) x (bp=lane&3); thread tile 4c x 4b.
// Acc layout: a[r][0] = row c0+r x (b0,b0+1) ; a[r][1] = row c0+r x (b0+2,b0+3).
static __device__ __forceinline__ void mm_acc(const ull* __restrict__ sG,
    const float* __restrict__ hb, int c0, int bloc, ull a[4][2]){
  #pragma unroll 8
  for (int k = 0; k < CC; k++){
    ulonglong2 g01 = *(const ulonglong2*)(sG + k*GSU + c0);
    ulonglong2 g23 = *(const ulonglong2*)(sG + k*GSU + c0 + 2);
    ulonglong2 hq  = *(const ulonglong2*)(hb + k*HS + bloc);
    fma2(a[0][0], g01.x, hq.x); fma2(a[0][1], g01.x, hq.y);
    fma2(a[1][0], g01.y, hq.x); fma2(a[1][1], g01.y, hq.y);
    fma2(a[2][0], g23.x, hq.x); fma2(a[2][1], g23.x, hq.y);
    fma2(a[3][0], g23.y, hq.x); fma2(a[3][1], g23.y, hq.y);
  }
}

// ---------- kernel 2: persistent DAG recurrence; role-split v/h warps ----------
// CTA = (dir, column), 256 thr. w = role*4 + cpart*2 + half.
// role 0 (v): acc = x + Gv@hA ; merge h-partial ; relu ; publish ; release ; writeback hA.
// role 1 (h): poll flag ; stage hB ; hacc = Gh@hB ; STS partial.
extern __shared__ float smem_dyn[];

__global__ void __launch_bounds__(256, 2) k_dag(
    const float* __restrict__ w0v, const float* __restrict__ w0h,
    const float* __restrict__ w1v, const float* __restrict__ w1h,
    const float* __restrict__ w2v, const float* __restrict__ w2h,
    const float* __restrict__ w3v, const float* __restrict__ w3h)
{
  const int bid  = blockIdx.x;
  const int dir  = bid & 3;          // interleaved: dep (dir,jcol-1) = bid-4 < bid
  const int jcol = bid >> 2;
  const int tid  = threadIdx.x;

  const float* gvp; const float* ghp;
  int fi, fj, doRelu;
  switch (dir){
    case 0:  gvp=w0v; ghp=w0h; fi=0; fj=0; doRelu=1; break;  // SE
    case 1:  gvp=w1v; ghp=w1h; fi=1; fj=0; doRelu=1; break;  // NE
    case 2:  gvp=w2v; ghp=w2h; fi=1; fj=1; doRelu=1; break;  // NW
    default: gvp=w3v; ghp=w3h; fi=0; fj=1; doRelu=0; break;  // SW (no ReLU in reference)
  }

  ull*   sGv   = (ull*)smem_dyn;                 // [k][c] splatted, CC*GSU ull (33,792 B each)
  ull*   sGh   = sGv + CC*GSU;
  float* hAb   = (float*)(sGh + CC*GSU);         // [half][CC][HS]  (2 x 5,120 B)
  float* hBb   = hAb + 2*CC*HS;                  // [half][CC][HS]
  ull*   Pb    = (ull*)(hBb + 2*CC*HS);          // partial: [cpart*2+half][256] ull (8,192 B)

  for (int idx = tid; idx < 4096; idx += 256){
    int c = idx >> 6, k = idx & 63;              // idx = c*64 + k (row-major source)
    sGv[k*GSU + c] = splat2(gvp[idx]);
    sGh[k*GSU + c] = splat2(ghp[idx]);
  }
  for (int idx = tid; idx < 2*CC*HS; idx += 256) hAb[idx] = 0.f;   // zero vertical state
  __syncthreads();

  const int lane  = tid & 31, w = tid >> 5;
  const int role  = w >> 2, cpart = (w >> 1) & 1, half = w & 1;
  const int cg = lane >> 2, bp = lane & 3;
  const int c0   = cpart*32 + cg*4;
  const int bloc = bp*4;                         // local b within 16-wide half
  const int b0g  = half*16 + bloc;               // global b
  const int tRow = cpart*32 + lane;              // h-warp staging k-row

  float* hA = hAb + half*CC*HS;
  float* hB = hBb + half*CC*HS;
  ull* Ptile = Pb + (cpart*2 + half)*256;

  float* out_dir = g_hf[dir];
  const int rj  = fj ? (WW-1-jcol) : jcol;
  const int rjL = fj ? (WW-jcol)   : (jcol-1);
  const int q = cpart*2 + half;                  // flag slot (same formula producer+consumer)
  const int* pflag = &g_cnt[dir][(jcol > 0) ? (jcol-1) : 0][q];
  int* mflag = &g_cnt[dir][jcol][q];
  const bool hasLeft = (jcol > 0);

  const int idV = 1 + half;                      // v-pair bar (2 rendezvous/iter)
  const int idH = 3 + half;                      // h-pair bar (2 rendezvous/iter)
  const int idA = 5 + q;                         // merge pair: v read-done
  const int idB = 9 + q;                         // merge pair: partial ready

  if (role == 1){
    // ================= h-warps =================
    if (!hasLeft) return;                        // column 0 has no horizontal term
    for (int i = 0; i < HH; i++){
      const int ri = fi ? (HH-1-i) : i;

      // poll producer flag (one address), then stage its 32-row slice
      const int need = i + 1;
      while (ld_acq(pflag) < need) { }
      const float* src = out_dir + (ri*WW + rjL)*CELL + tRow*BB + half*16;
      float4 l0 = *(const float4*)(src);
      float4 l1 = *(const float4*)(src + 4);
      float4 l2 = *(const float4*)(src + 8);
      float4 l3 = *(const float4*)(src + 12);
      float* dst = hB + tRow*HS;
      *(float4*)(dst + 0)  = l0;
      *(float4*)(dst + 4)  = l1;
      *(float4*)(dst + 8)  = l2;
      *(float4*)(dst + 12) = l3;
      bar64(idH);                                // both h-warps staged -> hB complete

      ull hacc[4][2] = {{0,0},{0,0},{0,0},{0,0}};
      mm_acc(sGh, hB, c0, bloc, hacc);
      bar64(idH);                                // both h-warps done reading hB (safe restage)

      if (i > 0) bar64(idA);                     // v finished reading partial(i-1)
      #pragma unroll
      for (int u = 0; u < 8; u++)                // conflict-free STS.64
        Ptile[u*32 + lane] = hacc[u>>1][u&1];
      bar64(idB);                                // partial(i) ready
    }
    return;
  }

  // ================= v-warps =================
  ulonglong2 xp[4];
  {
    const int ri0 = fi ? (HH-1) : 0;
    const float* xc = g_xT + (ri0*WW + rj)*CELL;
    #pragma unroll
    for (int r = 0; r < 4; r++)
      xp[r] = *(const ulonglong2*)(xc + (c0+r)*BB + b0g);
  }

  for (int i = 0; i < HH; i++){
    const int ri = fi ? (HH-1-i) : i;

    bar64(idV);                                  // partner v-warp writeback(i-1) visible

    ull a[4][2];
    #pragma unroll
    for (int r = 0; r < 4; r++){ a[r][0] = xp[r].x; a[r][1] = xp[r].y; }
    mm_acc(sGv, hA, c0, bloc, a);

    // prefetch x for next row (hidden under merge wait)
    if (i + 1 < HH){
      const int rin = fi ? (HH-2-i) : (i+1);
      const float* xc = g_xT + (rin*WW + rj)*CELL;
      #pragma unroll
      for (int r = 0; r < 4; r++)
        xp[r] = *(const ulonglong2*)(xc + (c0+r)*BB + b0g);
    }

    bar64(idV);                                  // partner done reading hA -> writeback safe below

    if (hasLeft){
      bar64(idB);                                // h partial(i) ready
      #pragma unroll
      for (int u = 0; u < 8; u++){
        ull p = Ptile[u*32 + lane];
        add2(a[u>>1][u&1], p);
      }
    }

    // epilogue: unpack, ReLU
    float o[4][4];                               // o[r][bb] = h[c0+r][b0g+bb]
    #pragma unroll
    for (int r = 0; r < 4; r++){
      unpack2(a[r][0], o[r][0], o[r][1]);
      unpack2(a[r][1], o[r][2], o[r][3]);
    }
    if (doRelu){
      #pragma unroll
      for (int r = 0; r < 4; r++)
        #pragma unroll
        for (int bb = 0; bb < 4; bb++)
          o[r][bb] = fmaxf(o[r][bb], 0.f);
    }

    // publish to gmem, release per-tile flag
    float* ocell = out_dir + (ri*WW + rj)*CELL;
    #pragma unroll
    for (int r = 0; r < 4; r++)
      *(float4*)(ocell + (c0+r)*BB + b0g) = make_float4(o[r][0], o[r][1], o[r][2], o[r][3]);
    __syncwarp();                                // order warp's STGs before lane0's release
    if (lane == 0) st_rel(mflag, i + 1);

    // vertical state writeback (safe: both v-warps past 2nd idV)
    #pragma unroll
    for (int r = 0; r < 4; r++)
      *(float4*)(hA + (c0+r)*HS + bloc) = make_float4(o[r][0], o[r][1], o[r][2], o[r][3]);

    if (hasLeft && i + 1 < HH) bar64(idA);       // signal: partial(i) consumed
  }
}

// ---------- kernel 3: out[b][c][i][j] = sum over 4 dirs of g_hf[d][i][j][c][b] ----------
__global__ void __launch_bounds__(256) k_sum(float* __restrict__ out){
  int bid = blockIdx.x;              // 800 blocks: (i, j-tile of 8)
  int i  = bid / 10;
  int j0 = (bid % 10) * 8;
  int t  = threadIdx.x;
  int p0 = t * 8;                    // fixed c, 8 consecutive b
  int c  = p0 >> 5;
  int b0 = p0 & 31;

  float v[8][8];
  #pragma unroll
  for (int jj = 0; jj < 8; jj++){
    int cell = (i*WW + j0 + jj)*CELL;
    float4 s0 = make_float4(0.f,0.f,0.f,0.f);
    float4 s1 = make_float4(0.f,0.f,0.f,0.f);
    #pragma unroll
    for (int d = 0; d < 4; d++){
      const float* src = g_hf[d] + cell + p0;
      float4 q0 = *(const float4*)src;
      float4 q1 = *(const float4*)(src + 4);
      s0.x += q0.x; s0.y += q0.y; s0.z += q0.z; s0.w += q0.w;
      s1.x += q1.x; s1.y += q1.y; s1.z += q1.z; s1.w += q1.w;
    }
    v[0][jj]=s0.x; v[1][jj]=s0.y; v[2][jj]=s0.z; v[3][jj]=s0.w;
    v[4][jj]=s1.x; v[5][jj]=s1.y; v[6][jj]=s1.z; v[7][jj]=s1.w;
  }
  #pragma unroll
  for (int pi = 0; pi < 8; pi++){
    float* dst = out + ((b0+pi)*CC + c)*NCELLS + i*WW + j0;
    *(float4*)dst     = make_float4(v[pi][0], v[pi][1], v[pi][2], v[pi][3]);
    *(float4*)(dst+4) = make_float4(v[pi][4], v[pi][5], v[pi][6], v[pi][7]);
  }
}

extern "C" void kernel_launch(void* const* d_in, const int* in_sizes, int n_in,
                              void* d_out, int out_size){
  const float* x   = (const float*)d_in[0];
  const float* g1  = (const float*)d_in[1];
  const float* g2  = (const float*)d_in[2];
  const float* g4  = (const float*)d_in[3];
  const float* g5  = (const float*)d_in[4];
  const float* g7  = (const float*)d_in[5];
  const float* g8  = (const float*)d_in[6];
  const float* g10 = (const float*)d_in[7];
  const float* g11 = (const float*)d_in[8];

  // G 67,584 + hA/hB 20,480 + partial 8,192 = 96,256 B -> 2 CTAs/SM
  const int smem_bytes = 2*CC*GSU*8 + 4*CC*HS*4 + 4*256*8;
  (void)cudaFuncSetAttribute(k_dag, cudaFuncAttributeMaxDynamicSharedMemorySize, smem_bytes);

  k_transpose<<<800, 256>>>(x);
  k_dag<<<4*WW, 256, smem_bytes>>>(g1, g2, g4, g5, g7, g8, g10, g11);
  k_sum<<<800, 256>>>((float*)d_out);
}

// round 12
// speedup vs baseline: 1.4260x; 1.0285x over previous
#include <cuda_runtime.h>

#define CC 64
#define BB 32
#define HH 80
#define WW 80
#define CELL (CC*BB)      // 2048 floats per cell tile
#define NCELLS (HH*WW)    // 6400 cells
#define GS 68             // float G smem row stride (R4-proven, 16B-aligned)
#define HS 20             // h buffer row stride in floats

// Static device scratch (allocation-free per harness rules)
__device__ float g_xT[NCELLS*CELL];          // x transposed to [i][j][c][b]
__device__ float g_hf[4][NCELLS*CELL];       // per-direction h fields, [i][j][c][b]
__device__ int   g_cnt[4][WW][4];            // per-(dir,col,(cpart,half)) rows-completed flags

typedef unsigned long long ull;

// ---------- packed-f32x2 helpers ----------
static __device__ __forceinline__ ull splat2(float x){
  unsigned int r = __float_as_uint(x);
  ull d; asm("mov.b64 %0, {%1,%2};" : "=l"(d) : "r"(r), "r"(r));
  return d;
}
static __device__ __forceinline__ void fma2(ull &d, ull a, ull b){
  asm("fma.rn.f32x2 %0, %1, %2, %0;" : "+l"(d) : "l"(a), "l"(b));
}
static __device__ __forceinline__ void add2(ull &d, ull a){
  asm("add.rn.f32x2 %0, %0, %1;" : "+l"(d) : "l"(a));
}
static __device__ __forceinline__ void unpack2(ull v, float &lo, float &hi){
  unsigned int a, b;
  asm("mov.b64 {%0,%1}, %2;" : "=r"(a), "=r"(b) : "l"(v));
  lo = __uint_as_float(a); hi = __uint_as_float(b);
}
static __device__ __forceinline__ int ld_acq(const int* p){
  int v; asm volatile("ld.global.acquire.gpu.b32 %0, [%1];" : "=r"(v) : "l"(p)); return v;
}
static __device__ __forceinline__ void st_rel(int* p, int v){
  asm volatile("st.global.release.gpu.b32 [%0], %1;" :: "l"(p), "r"(v));
}
static __device__ __forceinline__ void bar64(int id){
  asm volatile("bar.sync %0, 64;" :: "r"(id) : "memory");
}

// ---------- kernel 1: transpose x [B,C,H,W] -> g_xT [i][j][c][b]; zero flags ----------
__global__ void __launch_bounds__(256) k_transpose(const float* __restrict__ x){
  int bid = blockIdx.x;              // 800 blocks: (i, j-tile of 8)
  int i  = bid / 10;
  int j0 = (bid % 10) * 8;
  int t  = threadIdx.x;

  if (bid == 0){
    for (int z = t; z < 4*WW*4; z += 256) ((int*)g_cnt)[z] = 0;
  }

  int p0 = t * 8;                    // p = c*32 + b ; 8 consecutive p = fixed c, 8 b's
  int c  = p0 >> 5;
  int b0 = p0 & 31;

  float v[8][8];
  #pragma unroll
  for (int pi = 0; pi < 8; pi++){
    const float* src = x + (((b0+pi)*CC + c)*HH + i)*WW + j0;
    float4 q0 = *(const float4*)src;
    float4 q1 = *(const float4*)(src + 4);
    v[pi][0]=q0.x; v[pi][1]=q0.y; v[pi][2]=q0.z; v[pi][3]=q0.w;
    v[pi][4]=q1.x; v[pi][5]=q1.y; v[pi][6]=q1.z; v[pi][7]=q1.w;
  }
  #pragma unroll
  for (int jj = 0; jj < 8; jj++){
    float* dst = g_xT + (i*WW + j0 + jj)*CELL + p0;
    *(float4*)dst     = make_float4(v[0][jj], v[1][jj], v[2][jj], v[3][jj]);
    *(float4*)(dst+4) = make_float4(v[4][jj], v[5][jj], v[6][jj], v[7][jj]);
  }
}

// ---------- inner matmul (float G in smem, in-register splat; proven acc layout) ----------
// Warp tile 32c x 16b; lane = (cg=lane>>2) x (bp=lane&3); thread tile 4c x 4b.
// Acc layout: a[r][0] = row c0+r x (b0,b0+1) ; a[r][1] = row c0+r x (b0+2,b0+3).
// 14 instr / 32 FMA: 2x LDS.128 + 4x MOV(splat, alu pipe) + 8x FFMA2.
static __device__ __forceinline__ void mm_acc(const float* __restrict__ sG,
    const float* __restrict__ hb, int c0, int bloc, ull a[4][2]){
  #pragma unroll 8
  for (int k = 0; k < CC; k++){
    float4 gq = *(const float4*)(sG + k*GS + c0);           // G[c0..c0+3][k]
    ulonglong2 hq = *(const ulonglong2*)(hb + k*HS + bloc); // pairs (b0,b0+1),(b0+2,b0+3)
    ull g0 = splat2(gq.x), g1 = splat2(gq.y), g2 = splat2(gq.z), g3 = splat2(gq.w);
    fma2(a[0][0], g0, hq.x); fma2(a[0][1], g0, hq.y);
    fma2(a[1][0], g1, hq.x); fma2(a[1][1], g1, hq.y);
    fma2(a[2][0], g2, hq.x); fma2(a[2][1], g2, hq.y);
    fma2(a[3][0], g3, hq.x); fma2(a[3][1], g3, hq.y);
  }
}

// ---------- kernel 2: persistent DAG recurrence; role-split v/h warps; 3 CTAs/SM ----------
// CTA = (dir, column), 256 thr. w = role*4 + cpart*2 + half.
// role 0 (v): acc = x + Gv@hA ; merge h-partial ; relu ; publish ; release ; writeback hA.
// role 1 (h): poll flag ; stage hB ; hacc = Gh@hB ; STS partial.
extern __shared__ float smem_dyn[];

__global__ void __launch_bounds__(256, 3) k_dag(
    const float* __restrict__ w0v, const float* __restrict__ w0h,
    const float* __restrict__ w1v, const float* __restrict__ w1h,
    const float* __restrict__ w2v, const float* __restrict__ w2h,
    const float* __restrict__ w3v, const float* __restrict__ w3h)
{
  const int bid  = blockIdx.x;
  const int dir  = bid & 3;          // interleaved: dep (dir,jcol-1) = bid-4 < bid
  const int jcol = bid >> 2;
  const int tid  = threadIdx.x;

  const float* gvp; const float* ghp;
  int fi, fj, doRelu;
  switch (dir){
    case 0:  gvp=w0v; ghp=w0h; fi=0; fj=0; doRelu=1; break;  // SE
    case 1:  gvp=w1v; ghp=w1h; fi=1; fj=0; doRelu=1; break;  // NE
    case 2:  gvp=w2v; ghp=w2h; fi=1; fj=1; doRelu=1; break;  // NW
    default: gvp=w3v; ghp=w3h; fi=0; fj=1; doRelu=0; break;  // SW (no ReLU in reference)
  }

  float* sGv   = smem_dyn;                       // [k][c] float, CC*GS (17,408 B each)
  float* sGh   = sGv + CC*GS;
  float* hAb   = sGh + CC*GS;                    // [half][CC][HS]  (2 x 5,120 B)
  float* hBb   = hAb + 2*CC*HS;                  // [half][CC][HS]
  ull*   Pb    = (ull*)(hBb + 2*CC*HS);          // partial: [cpart*2+half][256] ull (8,192 B)

  for (int idx = tid; idx < 4096; idx += 256){
    int c = idx >> 6, k = idx & 63;              // idx = c*64 + k (row-major source)
    sGv[k*GS + c] = gvp[idx];
    sGh[k*GS + c] = ghp[idx];
  }
  for (int idx = tid; idx < 2*CC*HS; idx += 256) hAb[idx] = 0.f;   // zero vertical state
  __syncthreads();

  const int lane  = tid & 31, w = tid >> 5;
  const int role  = w >> 2, cpart = (w >> 1) & 1, half = w & 1;
  const int cg = lane >> 2, bp = lane & 3;
  const int c0   = cpart*32 + cg*4;
  const int bloc = bp*4;                         // local b within 16-wide half
  const int b0g  = half*16 + bloc;               // global b
  const int tRow = cpart*32 + lane;              // h-warp staging k-row

  float* hA = hAb + half*CC*HS;
  float* hB = hBb + half*CC*HS;
  ull* Ptile = Pb + (cpart*2 + half)*256;

  float* out_dir = g_hf[dir];
  const int rj  = fj ? (WW-1-jcol) : jcol;
  const int rjL = fj ? (WW-jcol)   : (jcol-1);
  const int q = cpart*2 + half;                  // flag slot (same formula producer+consumer)
  const int* pflag = &g_cnt[dir][(jcol > 0) ? (jcol-1) : 0][q];
  int* mflag = &g_cnt[dir][jcol][q];
  const bool hasLeft = (jcol > 0);

  const int idV = 1 + half;                      // v-pair bar (2 rendezvous/iter)
  const int idH = 3 + half;                      // h-pair bar (2 rendezvous/iter)
  const int idA = 5 + q;                         // merge pair: v read-done
  const int idB = 9 + q;                         // merge pair: partial ready

  if (role == 1){
    // ================= h-warps =================
    if (!hasLeft) return;                        // column 0 has no horizontal term
    for (int i = 0; i < HH; i++){
      const int ri = fi ? (HH-1-i) : i;

      // poll producer flag (one address), then stage its 32-row slice
      const int need = i + 1;
      while (ld_acq(pflag) < need) { }
      const float* src = out_dir + (ri*WW + rjL)*CELL + tRow*BB + half*16;
      float4 l0 = *(const float4*)(src);
      float4 l1 = *(const float4*)(src + 4);
      float4 l2 = *(const float4*)(src + 8);
      float4 l3 = *(const float4*)(src + 12);
      float* dst = hB + tRow*HS;
      *(float4*)(dst + 0)  = l0;
      *(float4*)(dst + 4)  = l1;
      *(float4*)(dst + 8)  = l2;
      *(float4*)(dst + 12) = l3;
      bar64(idH);                                // both h-warps staged -> hB complete

      ull hacc[4][2] = {{0,0},{0,0},{0,0},{0,0}};
      mm_acc(sGh, hB, c0, bloc, hacc);
      bar64(idH);                                // both h-warps done reading hB (safe restage)

      if (i > 0) bar64(idA);                     // v finished reading partial(i-1)
      #pragma unroll
      for (int u = 0; u < 8; u++)                // conflict-free STS.64
        Ptile[u*32 + lane] = hacc[u>>1][u&1];
      bar64(idB);                                // partial(i) ready
    }
    return;
  }

  // ================= v-warps =================
  ulonglong2 xp[4];
  {
    const int ri0 = fi ? (HH-1) : 0;
    const float* xc = g_xT + (ri0*WW + rj)*CELL;
    #pragma unroll
    for (int r = 0; r < 4; r++)
      xp[r] = *(const ulonglong2*)(xc + (c0+r)*BB + b0g);
  }

  for (int i = 0; i < HH; i++){
    const int ri = fi ? (HH-1-i) : i;

    bar64(idV);                                  // partner v-warp writeback(i-1) visible

    ull a[4][2];
    #pragma unroll
    for (int r = 0; r < 4; r++){ a[r][0] = xp[r].x; a[r][1] = xp[r].y; }
    mm_acc(sGv, hA, c0, bloc, a);

    // prefetch x for next row (hidden under merge wait)
    if (i + 1 < HH){
      const int rin = fi ? (HH-2-i) : (i+1);
      const float* xc = g_xT + (rin*WW + rj)*CELL;
      #pragma unroll
      for (int r = 0; r < 4; r++)
        xp[r] = *(const ulonglong2*)(xc + (c0+r)*BB + b0g);
    }

    bar64(idV);                                  // partner done reading hA -> writeback safe below

    if (hasLeft){
      bar64(idB);                                // h partial(i) ready
      #pragma unroll
      for (int u = 0; u < 8; u++){
        ull p = Ptile[u*32 + lane];
        add2(a[u>>1][u&1], p);
      }
    }

    // epilogue: unpack, ReLU
    float o[4][4];                               // o[r][bb] = h[c0+r][b0g+bb]
    #pragma unroll
    for (int r = 0; r < 4; r++){
      unpack2(a[r][0], o[r][0], o[r][1]);
      unpack2(a[r][1], o[r][2], o[r][3]);
    }
    if (doRelu){
      #pragma unroll
      for (int r = 0; r < 4; r++)
        #pragma unroll
        for (int bb = 0; bb < 4; bb++)
          o[r][bb] = fmaxf(o[r][bb], 0.f);
    }

    // publish to gmem, release per-tile flag
    float* ocell = out_dir + (ri*WW + rj)*CELL;
    #pragma unroll
    for (int r = 0; r < 4; r++)
      *(float4*)(ocell + (c0+r)*BB + b0g) = make_float4(o[r][0], o[r][1], o[r][2], o[r][3]);
    __syncwarp();                                // order warp's STGs before lane0's release
    if (lane == 0) st_rel(mflag, i + 1);

    // vertical state writeback (safe: both v-warps past 2nd idV)
    #pragma unroll
    for (int r = 0; r < 4; r++)
      *(float4*)(hA + (c0+r)*HS + bloc) = make_float4(o[r][0], o[r][1], o[r][2], o[r][3]);

    if (hasLeft && i + 1 < HH) bar64(idA);       // signal: partial(i) consumed
  }
}

// ---------- kernel 3: out[b][c][i][j] = sum over 4 dirs of g_hf[d][i][j][c][b] ----------
__global__ void __launch_bounds__(256) k_sum(float* __restrict__ out){
  int bid = blockIdx.x;              // 800 blocks: (i, j-tile of 8)
  int i  = bid / 10;
  int j0 = (bid % 10) * 8;
  int t  = threadIdx.x;
  int p0 = t * 8;                    // fixed c, 8 consecutive b
  int c  = p0 >> 5;
  int b0 = p0 & 31;

  float v[8][8];
  #pragma unroll
  for (int jj = 0; jj < 8; jj++){
    int cell = (i*WW + j0 + jj)*CELL;
    float4 s0 = make_float4(0.f,0.f,0.f,0.f);
    float4 s1 = make_float4(0.f,0.f,0.f,0.f);
    #pragma unroll
    for (int d = 0; d < 4; d++){
      const float* src = g_hf[d] + cell + p0;
      float4 q0 = *(const float4*)src;
      float4 q1 = *(const float4*)(src + 4);
      s0.x += q0.x; s0.y += q0.y; s0.z += q0.z; s0.w += q0.w;
      s1.x += q1.x; s1.y += q1.y; s1.z += q1.z; s1.w += q1.w;
    }
    v[0][jj]=s0.x; v[1][jj]=s0.y; v[2][jj]=s0.z; v[3][jj]=s0.w;
    v[4][jj]=s1.x; v[5][jj]=s1.y; v[6][jj]=s1.z; v[7][jj]=s1.w;
  }
  #pragma unroll
  for (int pi = 0; pi < 8; pi++){
    float* dst = out + ((b0+pi)*CC + c)*NCELLS + i*WW + j0;
    *(float4*)dst     = make_float4(v[pi][0], v[pi][1], v[pi][2], v[pi][3]);
    *(float4*)(dst+4) = make_float4(v[pi][4], v[pi][5], v[pi][6], v[pi][7]);
  }
}

extern "C" void kernel_launch(void* const* d_in, const int* in_sizes, int n_in,
                              void* d_out, int out_size){
  const float* x   = (const float*)d_in[0];
  const float* g1  = (const float*)d_in[1];
  const float* g2  = (const float*)d_in[2];
  const float* g4  = (const float*)d_in[3];
  const float* g5  = (const float*)d_in[4];
  const float* g7  = (const float*)d_in[5];
  const float* g8  = (const float*)d_in[6];
  const float* g10 = (const float*)d_in[7];
  const float* g11 = (const float*)d_in[8];

  // G 34,816 + hA/hB 20,480 + partial 8,192 = 63,488 B -> 3 CTAs/SM (full residency)
  const int smem_bytes = 2*CC*GS*4 + 4*CC*HS*4 + 4*256*8;
  (void)cudaFuncSetAttribute(k_dag, cudaFuncAttributeMaxDynamicSharedMemorySize, smem_bytes);

  k_transpose<<<800, 256>>>(x);
  k_dag<<<4*WW, 256, smem_bytes>>>(g1, g2, g4, g5, g7, g8, g10, g11);
  k_sum<<<800, 256>>>((float*)d_out);
}